// round 1
// baseline (speedup 1.0000x reference)
#include <cuda_runtime.h>
#include <math_constants.h>

// ChamferDistance: x (8,8192,3) f32, y (8,8192,3) f32 -> scalar f32.
// Brute-force 8192x8192 per batch, both directions, min/mean/max/sum.
//
// Strategy: issue/FMA-pipe bound kernel using packed fma.rn.f32x2 (FFMA2).
//   d^2(q,r) = qq + (rr - 2*dot(q,r));  qq hoisted, rr pre-baked into smem tile.
//   min(sqrt(v+EPS)) == sqrt(min(v)+EPS)  -> sqrt only once per point.
// Two symmetric passes (grid.z = direction), R-loop split 4 ways for occupancy,
// partial mins in __device__ scratch (no atomics, no init kernel needed).

#define BATCH   8
#define NPTS    8192
#define RSPLIT  4
#define TPB     256
#define U       4              // queries per thread
#define QBLK    (BATCH * NPTS / (TPB * U))   // 64
#define TR      256            // reference points per smem tile
#define RCHUNK  (NPTS / RSPLIT)              // 2048
#define EPS_F   1e-10f

__device__ float g_minpart[2][RSPLIT][BATCH * NPTS];
__device__ float g_means[2][BATCH];

__device__ __forceinline__ unsigned long long f2_mul(unsigned long long a, unsigned long long b) {
    unsigned long long d;
    asm("mul.rn.f32x2 %0, %1, %2;" : "=l"(d) : "l"(a), "l"(b));
    return d;
}
__device__ __forceinline__ unsigned long long f2_fma(unsigned long long a, unsigned long long b, unsigned long long c) {
    unsigned long long d;
    asm("fma.rn.f32x2 %0, %1, %2, %3;" : "=l"(d) : "l"(a), "l"(b), "l"(c));
    return d;
}
__device__ __forceinline__ unsigned long long f2_pack(float a, float b) {
    unsigned long long r;
    asm("mov.b64 %0, {%1, %2};" : "=l"(r) : "f"(a), "f"(b));
    return r;
}
__device__ __forceinline__ void f2_unpack(unsigned long long v, float& lo, float& hi) {
    asm("mov.b64 {%0, %1}, %2;" : "=f"(lo), "=f"(hi) : "l"(v));
}

__global__ __launch_bounds__(TPB)
void chamfer_pass_kernel(const float* __restrict__ x, const float* __restrict__ y) {
    const int dir = blockIdx.z;
    const float* __restrict__ Q = dir ? y : x;   // query side
    const float* __restrict__ R = dir ? x : y;   // reference side

    const int qbase = blockIdx.x * (TPB * U);    // 1024 queries per block, within one batch
    const int b     = qbase / NPTS;
    const int r0    = blockIdx.y * RCHUNK;
    const int r1    = r0 + RCHUNK;
    const int t     = threadIdx.x;

    // Pair-interleaved tile: for pair j (points 2j, 2j+1):
    //   sm[8j+0..1] = x pair, sm[8j+2..3] = y pair, sm[8j+4..5] = z pair, sm[8j+6..7] = rr pair
    __shared__ float sm[TR * 4];

    float qq[U], minv[U];
    unsigned long long qx2[U], qy2[U], qz2[U];
#pragma unroll
    for (int u = 0; u < U; u++) {
        const float* p = Q + (size_t)(qbase + u * TPB + t) * 3;
        float a = p[0], c = p[1], e = p[2];
        qq[u]  = a * a + c * c + e * e;
        qx2[u] = f2_pack(a, a);
        qy2[u] = f2_pack(c, c);
        qz2[u] = f2_pack(e, e);
        minv[u] = CUDART_INF_F;
    }
    const unsigned long long NEG2 = f2_pack(-2.0f, -2.0f);

    const float* __restrict__ Rb = R + (size_t)b * NPTS * 3;

    for (int rt = r0; rt < r1; rt += TR) {
        __syncthreads();
        {
            const float* rp = Rb + (size_t)(rt + t) * 3;   // TR == TPB: one point per thread
            float rx = rp[0], ry = rp[1], rz = rp[2];
            float rr = rx * rx + ry * ry + rz * rz;
            int j = t >> 1, s = t & 1;
            sm[8 * j + 0 + s] = rx;
            sm[8 * j + 2 + s] = ry;
            sm[8 * j + 4 + s] = rz;
            sm[8 * j + 6 + s] = rr;
        }
        __syncthreads();

#pragma unroll 4
        for (int j = 0; j < TR / 2; j++) {
            // Two LDS.128 -> four pre-packed 64-bit f32x2 operands (broadcast, conflict-free)
            ulonglong2 A  = *reinterpret_cast<const ulonglong2*>(&sm[8 * j]);      // {x-pair, y-pair}
            ulonglong2 Bv = *reinterpret_cast<const ulonglong2*>(&sm[8 * j + 4]);  // {z-pair, rr-pair}
#pragma unroll
            for (int u = 0; u < U; u++) {
                unsigned long long acc = f2_mul(qx2[u], A.x);
                acc = f2_fma(qy2[u], A.y, acc);
                acc = f2_fma(qz2[u], Bv.x, acc);
                unsigned long long v2 = f2_fma(acc, NEG2, Bv.y);   // rr - 2*dot (packed x2)
                float lo, hi;
                f2_unpack(v2, lo, hi);
                minv[u] = fminf(minv[u], lo);
                minv[u] = fminf(minv[u], hi);
            }
        }
    }

#pragma unroll
    for (int u = 0; u < U; u++) {
        g_minpart[dir][blockIdx.y][qbase + u * TPB + t] = minv[u] + qq[u];
    }
}

__global__ __launch_bounds__(TPB)
void chamfer_reduce_kernel() {
    const int dir = blockIdx.x >> 3;
    const int b   = blockIdx.x & 7;
    const int t   = threadIdx.x;

    float s = 0.0f;
    for (int n = t; n < NPTS; n += TPB) {
        const int q = b * NPTS + n;
        float v = g_minpart[dir][0][q];
#pragma unroll
        for (int r = 1; r < RSPLIT; r++) v = fminf(v, g_minpart[dir][r][q]);
        s += sqrtf(v + EPS_F);
    }

    __shared__ float red[TPB];
    red[t] = s;
    __syncthreads();
    for (int o = TPB / 2; o > 0; o >>= 1) {
        if (t < o) red[t] += red[t + o];
        __syncthreads();
    }
    if (t == 0) g_means[dir][b] = red[0] * (1.0f / (float)NPTS);
}

__global__ void chamfer_final_kernel(float* __restrict__ out) {
    float s = 0.0f;
#pragma unroll
    for (int b = 0; b < BATCH; b++) s += fmaxf(g_means[0][b], g_means[1][b]);
    *out = s;
}

extern "C" void kernel_launch(void* const* d_in, const int* in_sizes, int n_in,
                              void* d_out, int out_size) {
    const float* x = (const float*)d_in[0];
    const float* y = (const float*)d_in[1];
    float* out = (float*)d_out;

    dim3 grid(QBLK, RSPLIT, 2);
    chamfer_pass_kernel<<<grid, TPB>>>(x, y);
    chamfer_reduce_kernel<<<16, TPB>>>();
    chamfer_final_kernel<<<1, 1>>>(out);
}

// round 2
// speedup vs baseline: 1.3852x; 1.3852x over previous
#include <cuda_runtime.h>
#include <math_constants.h>

// ChamferDistance: x (8,8192,3) f32, y (8,8192,3) f32 -> scalar f32.
// FMA-pipe bound brute force with packed fma.rn.f32x2 (FFMA2).
//   d^2(q,r) = qq + (rr - 2*dot(q,r))
//   queries pre-scaled by -2, so per ref-pair: acc = fma(qx',rx2, rr2); fma; fma
//   min(sqrt(v+EPS)) == sqrt(min(v)+EPS) -> one sqrt per point at the end.
// Grid tuned for single-wave high occupancy: 2048 blocks x 128 threads.

#define BATCH   8
#define NPTS    8192
#define RSPLIT  8
#define TPB     128
#define U       4                              // queries per thread
#define QPB     (TPB * U)                      // 512 queries per block
#define QBLK    (BATCH * NPTS / QPB)           // 128
#define TR      128                            // reference points per smem tile
#define RCHUNK  (NPTS / RSPLIT)                // 1024
#define EPS_F   1e-10f

__device__ float g_minpart[2][RSPLIT][BATCH * NPTS];
__device__ float g_means[2][BATCH];

__device__ __forceinline__ unsigned long long f2_fma(unsigned long long a, unsigned long long b, unsigned long long c) {
    unsigned long long d;
    asm("fma.rn.f32x2 %0, %1, %2, %3;" : "=l"(d) : "l"(a), "l"(b), "l"(c));
    return d;
}
__device__ __forceinline__ unsigned long long f2_pack(float a, float b) {
    unsigned long long r;
    asm("mov.b64 %0, {%1, %2};" : "=l"(r) : "f"(a), "f"(b));
    return r;
}
__device__ __forceinline__ void f2_unpack(unsigned long long v, float& lo, float& hi) {
    asm("mov.b64 {%0, %1}, %2;" : "=f"(lo), "=f"(hi) : "l"(v));
}

__global__ __launch_bounds__(TPB)
void chamfer_pass_kernel(const float* __restrict__ x, const float* __restrict__ y) {
    const int dir = blockIdx.z;
    const float* __restrict__ Q = dir ? y : x;   // query side
    const float* __restrict__ R = dir ? x : y;   // reference side

    const int qbase = blockIdx.x * QPB;          // within one batch (8192/512=16 blocks/batch)
    const int b     = qbase / NPTS;
    const int r0    = blockIdx.y * RCHUNK;
    const int t     = threadIdx.x;

    // Pair-interleaved tile: for ref pair j (points 2j, 2j+1):
    //   sm[8j+0..1]=x pair, sm[8j+2..3]=y pair, sm[8j+4..5]=z pair, sm[8j+6..7]=rr pair
    __shared__ float sm[TR * 4];

    float qq[U], minv[U];
    unsigned long long qx2[U], qy2[U], qz2[U];   // query coords pre-scaled by -2, splatted
#pragma unroll
    for (int u = 0; u < U; u++) {
        const float* p = Q + (size_t)(qbase + u * TPB + t) * 3;
        float a = p[0], c = p[1], e = p[2];
        qq[u]  = a * a + c * c + e * e;
        a *= -2.0f; c *= -2.0f; e *= -2.0f;
        qx2[u] = f2_pack(a, a);
        qy2[u] = f2_pack(c, c);
        qz2[u] = f2_pack(e, e);
        minv[u] = CUDART_INF_F;
    }

    const float* __restrict__ Rb = R + (size_t)b * NPTS * 3;

    for (int rt = r0; rt < r0 + RCHUNK; rt += TR) {
        __syncthreads();
        {
            const float* rp = Rb + (size_t)(rt + t) * 3;   // TR == TPB: one point per thread
            float rx = rp[0], ry = rp[1], rz = rp[2];
            float rr = rx * rx + ry * ry + rz * rz;
            int j = t >> 1, s = t & 1;
            sm[8 * j + 0 + s] = rx;
            sm[8 * j + 2 + s] = ry;
            sm[8 * j + 4 + s] = rz;
            sm[8 * j + 6 + s] = rr;
        }
        __syncthreads();

#pragma unroll 8
        for (int j = 0; j < TR / 2; j++) {
            // Two LDS.128 -> four pre-packed f32x2 operands (broadcast, conflict-free)
            ulonglong2 A  = *reinterpret_cast<const ulonglong2*>(&sm[8 * j]);      // {x-pair, y-pair}
            ulonglong2 Bv = *reinterpret_cast<const ulonglong2*>(&sm[8 * j + 4]);  // {z-pair, rr-pair}
#pragma unroll
            for (int u = 0; u < U; u++) {
                unsigned long long acc = f2_fma(qx2[u], A.x, Bv.y);  // rr - 2 qx rx
                acc = f2_fma(qy2[u], A.y, acc);
                acc = f2_fma(qz2[u], Bv.x, acc);                     // rr - 2 dot (packed x2)
                float lo, hi;
                f2_unpack(acc, lo, hi);
                minv[u] = fminf(minv[u], lo);
                minv[u] = fminf(minv[u], hi);
            }
        }
    }

#pragma unroll
    for (int u = 0; u < U; u++) {
        g_minpart[dir][blockIdx.y][qbase + u * TPB + t] = minv[u] + qq[u];
    }
}

__global__ __launch_bounds__(256)
void chamfer_reduce_kernel() {
    const int dir = blockIdx.x >> 3;
    const int b   = blockIdx.x & 7;
    const int t   = threadIdx.x;

    float s = 0.0f;
    for (int n = t; n < NPTS; n += 256) {
        const int q = b * NPTS + n;
        float v = g_minpart[dir][0][q];
#pragma unroll
        for (int r = 1; r < RSPLIT; r++) v = fminf(v, g_minpart[dir][r][q]);
        s += sqrtf(v + EPS_F);
    }

    __shared__ float red[256];
    red[t] = s;
    __syncthreads();
    for (int o = 128; o > 0; o >>= 1) {
        if (t < o) red[t] += red[t + o];
        __syncthreads();
    }
    if (t == 0) g_means[dir][b] = red[0] * (1.0f / (float)NPTS);
}

__global__ void chamfer_final_kernel(float* __restrict__ out) {
    float s = 0.0f;
#pragma unroll
    for (int b = 0; b < BATCH; b++) s += fmaxf(g_means[0][b], g_means[1][b]);
    *out = s;
}

extern "C" void kernel_launch(void* const* d_in, const int* in_sizes, int n_in,
                              void* d_out, int out_size) {
    const float* x = (const float*)d_in[0];
    const float* y = (const float*)d_in[1];
    float* out = (float*)d_out;

    dim3 grid(QBLK, RSPLIT, 2);
    chamfer_pass_kernel<<<grid, TPB>>>(x, y);
    chamfer_reduce_kernel<<<16, 256>>>();
    chamfer_final_kernel<<<1, 1>>>(out);
}

// round 3
// speedup vs baseline: 1.4050x; 1.0143x over previous
#include <cuda_runtime.h>
#include <math_constants.h>

// ChamferDistance: x (8,8192,3) f32, y (8,8192,3) f32 -> scalar f32.
// FMA-pipe bound brute force with packed fma.rn.f32x2 (FFMA2).
//   d^2(q,r) = qq + (rr - 2*dot(q,r)); queries pre-scaled by -2.
//   min(sqrt(v+EPS)) == sqrt(min(v)+EPS) -> one sqrt per point at the end.
// R3: single-wave grid (1024 blocks <= 148*10 resident cap) + double-buffered
// smem tiles (prefetch LDG ahead of compute, one barrier per tile).

#define BATCH   8
#define NPTS    8192
#define RSPLIT  4
#define TPB     128
#define U       4                              // queries per thread
#define QPB     (TPB * U)                      // 512 queries per block
#define QBLK    (BATCH * NPTS / QPB)           // 128
#define TR      128                            // reference points per smem tile
#define RCHUNK  (NPTS / RSPLIT)                // 2048
#define NTILES  (RCHUNK / TR)                  // 16
#define EPS_F   1e-10f

__device__ float g_minpart[2][RSPLIT][BATCH * NPTS];
__device__ float g_partial[128];
__device__ float g_means[2][BATCH];

__device__ __forceinline__ unsigned long long f2_fma(unsigned long long a, unsigned long long b, unsigned long long c) {
    unsigned long long d;
    asm("fma.rn.f32x2 %0, %1, %2, %3;" : "=l"(d) : "l"(a), "l"(b), "l"(c));
    return d;
}
__device__ __forceinline__ unsigned long long f2_pack(float a, float b) {
    unsigned long long r;
    asm("mov.b64 %0, {%1, %2};" : "=l"(r) : "f"(a), "f"(b));
    return r;
}
__device__ __forceinline__ void f2_unpack(unsigned long long v, float& lo, float& hi) {
    asm("mov.b64 {%0, %1}, %2;" : "=f"(lo), "=f"(hi) : "l"(v));
}

__global__ __launch_bounds__(TPB)
void chamfer_pass_kernel(const float* __restrict__ x, const float* __restrict__ y) {
    const int dir = blockIdx.z;
    const float* __restrict__ Q = dir ? y : x;   // query side
    const float* __restrict__ R = dir ? x : y;   // reference side

    const int qbase = blockIdx.x * QPB;          // within one batch (16 blocks/batch)
    const int b     = qbase / NPTS;
    const int r0    = blockIdx.y * RCHUNK;
    const int t     = threadIdx.x;

    // Double-buffered pair-interleaved tiles: for ref pair j (points 2j, 2j+1):
    //   sm[buf][8j+0..1]=x pair, [8j+2..3]=y pair, [8j+4..5]=z pair, [8j+6..7]=rr pair
    __shared__ float sm[2][TR * 4];

    float qq[U], minv[U];
    unsigned long long qx2[U], qy2[U], qz2[U];   // query coords pre-scaled by -2, splatted
#pragma unroll
    for (int u = 0; u < U; u++) {
        const float* p = Q + (size_t)(qbase + u * TPB + t) * 3;
        float a = p[0], c = p[1], e = p[2];
        qq[u]  = a * a + c * c + e * e;
        a *= -2.0f; c *= -2.0f; e *= -2.0f;
        qx2[u] = f2_pack(a, a);
        qy2[u] = f2_pack(c, c);
        qz2[u] = f2_pack(e, e);
        minv[u] = CUDART_INF_F;
    }

    const float* __restrict__ Rb = R + (size_t)b * NPTS * 3;
    const int jj = (t >> 1) * 8 + (t & 1);       // interleave slot for this thread's ref point

    // Prologue: load tile 0 into registers, stage to buf 0.
    float rx, ry, rz;
    {
        const float* rp = Rb + (size_t)(r0 + t) * 3;   // TR == TPB
        rx = rp[0]; ry = rp[1]; rz = rp[2];
        sm[0][jj + 0] = rx;
        sm[0][jj + 2] = ry;
        sm[0][jj + 4] = rz;
        sm[0][jj + 6] = rx * rx + ry * ry + rz * rz;
    }
    __syncthreads();

#pragma unroll 1
    for (int tile = 0; tile < NTILES; tile++) {
        // Prefetch next tile (LDG latency hidden behind this tile's compute)
        if (tile + 1 < NTILES) {
            const float* rp = Rb + (size_t)(r0 + (tile + 1) * TR + t) * 3;
            rx = rp[0]; ry = rp[1]; rz = rp[2];
        }

        const float* smc = sm[tile & 1];
#pragma unroll 8
        for (int j = 0; j < TR / 2; j++) {
            // Two LDS.128 -> four pre-packed f32x2 operands (broadcast, conflict-free)
            ulonglong2 A  = *reinterpret_cast<const ulonglong2*>(&smc[8 * j]);      // {x-pair, y-pair}
            ulonglong2 Bv = *reinterpret_cast<const ulonglong2*>(&smc[8 * j + 4]);  // {z-pair, rr-pair}
#pragma unroll
            for (int u = 0; u < U; u++) {
                unsigned long long acc = f2_fma(qx2[u], A.x, Bv.y);  // rr - 2 qx rx
                acc = f2_fma(qy2[u], A.y, acc);
                acc = f2_fma(qz2[u], Bv.x, acc);                     // rr - 2 dot (packed x2)
                float lo, hi;
                f2_unpack(acc, lo, hi);
                minv[u] = fminf(minv[u], fminf(lo, hi));
            }
        }

        if (tile + 1 < NTILES) {
            float* smn = sm[(tile + 1) & 1];
            smn[jj + 0] = rx;
            smn[jj + 2] = ry;
            smn[jj + 4] = rz;
            smn[jj + 6] = rx * rx + ry * ry + rz * rz;
            __syncthreads();
        }
    }

#pragma unroll
    for (int u = 0; u < U; u++) {
        g_minpart[dir][blockIdx.y][qbase + u * TPB + t] = minv[u] + qq[u];
    }
}

// 128 blocks: dir(2) x batch(8) x chunk(8); each covers 1024 queries.
__global__ __launch_bounds__(256)
void chamfer_reduce_kernel() {
    const int dir   = blockIdx.x >> 6;
    const int b     = (blockIdx.x >> 3) & 7;
    const int chunk = blockIdx.x & 7;
    const int t     = threadIdx.x;

    float s = 0.0f;
#pragma unroll
    for (int k = 0; k < 4; k++) {
        const int q = b * NPTS + chunk * 1024 + k * 256 + t;
        float v = g_minpart[dir][0][q];
#pragma unroll
        for (int r = 1; r < RSPLIT; r++) v = fminf(v, g_minpart[dir][r][q]);
        s += sqrtf(v + EPS_F);
    }

    __shared__ float red[256];
    red[t] = s;
    __syncthreads();
    for (int o = 128; o > 0; o >>= 1) {
        if (t < o) red[t] += red[t + o];
        __syncthreads();
    }
    if (t == 0) g_partial[blockIdx.x] = red[0];
}

__global__ void chamfer_final_kernel(float* __restrict__ out) {
    float s = 0.0f;
#pragma unroll
    for (int b = 0; b < BATCH; b++) {
        float m0 = 0.0f, m1 = 0.0f;
#pragma unroll
        for (int c = 0; c < 8; c++) {
            m0 += g_partial[(0 << 6) | (b << 3) | c];
            m1 += g_partial[(1 << 6) | (b << 3) | c];
        }
        s += fmaxf(m0, m1) * (1.0f / (float)NPTS);
    }
    *out = s;
}

extern "C" void kernel_launch(void* const* d_in, const int* in_sizes, int n_in,
                              void* d_out, int out_size) {
    const float* x = (const float*)d_in[0];
    const float* y = (const float*)d_in[1];
    float* out = (float*)d_out;

    dim3 grid(QBLK, RSPLIT, 2);
    chamfer_pass_kernel<<<grid, TPB>>>(x, y);
    chamfer_reduce_kernel<<<128, 256>>>();
    chamfer_final_kernel<<<1, 1>>>(out);
}